// round 16
// baseline (speedup 1.0000x reference)
#include <cuda_runtime.h>
#include <cuda_bf16.h>
#include <math.h>
#include <stdint.h>

#define NN 1024
#define MM 64
#define LDA 1040
#define PP 64

__device__ float    g_cov[(size_t)MM * NN * LDA];
__device__ uint16_t g_pH[(size_t)MM * NN * PP];
__device__ uint16_t g_pL[(size_t)MM * NN * PP];
__device__ float    g_ld[(size_t)MM * 32 * 1056];
__device__ uint16_t g_iH[(size_t)MM * 32 * 1024];
__device__ uint16_t g_iL[(size_t)MM * 32 * 1024];
__device__ float    g_scal[MM * 8];
__device__ float    g_ldet[MM * 32];
__device__ float    g_xs[MM * 2048];

__device__ int      g_bcount_v = 0;
__device__ unsigned g_bsense_v = 0;

__device__ __forceinline__ void hmma(float* c, const uint32_t* a, const uint32_t* b) {
    asm volatile("mma.sync.aligned.m16n8k16.row.col.f32.bf16.bf16.f32 "
        "{%0,%1,%2,%3},{%4,%5,%6,%7},{%8,%9},{%0,%1,%2,%3};"
        : "+f"(c[0]), "+f"(c[1]), "+f"(c[2]), "+f"(c[3])
        : "r"(a[0]), "r"(a[1]), "r"(a[2]), "r"(a[3]), "r"(b[0]), "r"(b[1]));
}
__device__ __forceinline__ void cvt2(float xx, float yy, uint32_t& h, uint32_t& l) {
    __nv_bfloat16 h0 = __float2bfloat16(xx), h1 = __float2bfloat16(yy);
    __nv_bfloat16 l0 = __float2bfloat16(xx - __bfloat162float(h0));
    __nv_bfloat16 l1 = __float2bfloat16(yy - __bfloat162float(h1));
    h = (uint32_t)__bfloat16_as_ushort(h0) | ((uint32_t)__bfloat16_as_ushort(h1) << 16);
    l = (uint32_t)__bfloat16_as_ushort(l0) | ((uint32_t)__bfloat16_as_ushort(l1) << 16);
}
__device__ __forceinline__ float sp_(float x) {
    return fmaxf(x, 0.f) + log1pf(expf(-fabsf(x))) + 1e-7f;
}
__device__ __forceinline__ float log_normal_(float v, float mean, float s, float eps) {
    const float C = -0.91893853320467274178f;
    float d = v - mean;
    return -d * d / (2.f * s * s + eps) - logf(s) + C;
}
__device__ __forceinline__ float log_lognormal_(float v, float mean, float s, float eps) {
    const float C = -0.91893853320467274178f;
    float lv = logf(v);
    float d = lv - mean;
    return -d * d / (2.f * s * s + eps) - lv - logf(s) + C;
}

// grid-wide sense-reversing barrier (all blocks co-resident by occupancy)
__device__ __forceinline__ void gbar(unsigned& sense) {
    __syncthreads();
    if (threadIdx.x == 0) {
        unsigned target = sense ^ 1u;
        __threadfence();
        int v = atomicAdd(&g_bcount_v, 1);
        if (v == (int)gridDim.x - 1) {
            g_bcount_v = 0;
            __threadfence();
            *(volatile unsigned*)&g_bsense_v = target;
        } else {
            while (*(volatile unsigned*)&g_bsense_v != target) { }
            __threadfence();
        }
        sense = target;
    }
    __syncthreads();
}

// factor 32x32 (a[j] = row 'lane', zeros above diag) + invert, registers/shuffles only
__device__ __forceinline__ void wfactor_inv(float* a, int lane, float* gld, float* ldet,
                                            uint16_t* oH, uint16_t* oL)
{
    #pragma unroll
    for (int j = 0; j < 32; ++j) {
        float dj = __shfl_sync(0xffffffffu, a[j], j);
        float sj = sqrtf(dj);
        float lrj = (lane == j) ? sj : a[j] / sj;
        a[j] = lrj;
        #pragma unroll
        for (int cc = j + 1; cc < 32; ++cc)
            a[cc] -= lrj * __shfl_sync(0xffffffffu, lrj, cc);
    }
    #pragma unroll
    for (int j = 0; j < 32; ++j)
        if (j <= lane) gld[lane * 33 + j] = a[j];
    float ld = logf(a[lane]);
    #pragma unroll
    for (int o = 16; o; o >>= 1) ld += __shfl_xor_sync(0xffffffffu, ld, o);
    if (lane == 0) *ldet = ld;
    // invert: lane = column index
    float xv[32];
    #pragma unroll
    for (int i = 0; i < 32; ++i) {
        float s = (i == lane) ? 1.f : 0.f;
        #pragma unroll
        for (int p = 0; p < 32; ++p)
            if (p < i)
                s -= __shfl_sync(0xffffffffu, a[p], i) * xv[p];
        float dii = __shfl_sync(0xffffffffu, a[i], i);
        xv[i] = s / dii;
    }
    #pragma unroll
    for (int i = 0; i < 32; ++i) {
        __nv_bfloat16 h = __float2bfloat16(xv[i]);
        __nv_bfloat16 l = __float2bfloat16(xv[i] - __bfloat162float(h));
        oH[i * 32 + lane] = __bfloat16_as_ushort(h);
        oL[i * 32 + lane] = __bfloat16_as_ushort(l);
    }
}

extern "C" __global__ void __launch_bounds__(256, 2)
k_persist(const float* __restrict__ x, const float* __restrict__ y,
          const float* __restrict__ z,
          const float* qbm, const float* qbs, const float* qsm, const float* qss,
          const float* qem, const float* qes, const float* qzm, const float* qzs,
          const float* qnm, const float* qns, float* __restrict__ out)
{
    __shared__ float s_rhs[NN];
    __shared__ float s_red[256];

    const int tid = threadIdx.x;
    const int wid = tid >> 5, lane = tid & 31;
    const int g = lane >> 2, t = lane & 3;
    const int gt = blockIdx.x * 256 + tid;
    const int NT = gridDim.x * 256;
    const int gw = blockIdx.x * 8 + wid;
    const int NW = gridDim.x * 8;

    unsigned sense = 0;
    if (tid == 0) sense = *(volatile unsigned*)&g_bsense_v;

    // ===== phase: scalars =====
    if (gt < MM) {
        int m = gt;
        float s0 = sp_(sqrtf(logf(2.f)));
        float z0 = z[m*5+0], z1 = z[m*5+1], z2 = z[m*5+2], z3 = z[m*5+3], z4 = z[m*5+4];
        float sps = sp_(*qss), spb = sp_(*qbs), spe = sp_(*qes), spz = sp_(*qzs), spn = sp_(*qns);
        float sigma2 = expf(z0 * sps + *qsm);
        float beta   = z1 * spb + *qbm;
        float eta    = expf(z2 * spe + *qem);
        float lsZ    = expf(z3 * spz + *qzm);
        float lsN    = expf(z4 * spn + *qnm);
        float lp = log_normal_(beta, 0.f, 1.f, 1e-5f)
                 + log_lognormal_(sigma2, 1.f, s0, 1e-6f)
                 + log_lognormal_(eta,    1.f, s0, 1e-6f)
                 + log_lognormal_(lsZ,    1.f, s0, 1e-6f)
                 + log_lognormal_(lsN,    1.f, s0, 1e-6f);
        float lq = log_normal_(beta, *qbm, spb, 1e-5f)
                 + log_lognormal_(sigma2, *qsm, sps, 1e-6f)
                 + log_lognormal_(eta,    *qem, spe, 1e-6f)
                 + log_lognormal_(lsZ,    *qzm, spz, 1e-6f)
                 + log_lognormal_(lsN,    *qnm, spn, 1e-6f);
        g_scal[m*8+0] = beta; g_scal[m*8+1] = sigma2; g_scal[m*8+2] = eta;
        g_scal[m*8+3] = lsZ;  g_scal[m*8+4] = lsN;    g_scal[m*8+5] = lp - lq;
    }
    gbar(sense);

    // ===== phase: scaled x =====
    for (int k = gt; k < MM * 2048; k += NT) {
        int m = k >> 11, r = k & 2047;
        float v;
        if (r < 1024) v = x[2*r]       / g_scal[m*8+3];
        else          v = x[2*(r-1024)+1] / g_scal[m*8+4];
        g_xs[m * 2048 + r] = v;
    }
    gbar(sense);

    // ===== phase: cov build (one row per thread-job) =====
    for (int job = gt; job < MM * NN; job += NT) {
        int m = job >> 10, i = job & 1023;
        const float* xs0 = g_xs + m * 2048;
        const float* xs1 = xs0 + 1024;
        const float eta = g_scal[m*8+2], sigma2 = g_scal[m*8+1];
        float xi0 = xs0[i], xi1 = xs1[i];
        float* row = g_cov + (size_t)m * NN * LDA + (size_t)i * LDA;
        int j4 = i & ~3;
        for (int j = 0; j < j4; j += 4) {
            float4 a0 = *(const float4*)(xs0 + j);
            float4 a1 = *(const float4*)(xs1 + j);
            float4 o; float d0, d1;
            d0 = xi0 - a0.x; d1 = xi1 - a1.x; o.x = eta * __expf(-0.5f * (d0*d0 + d1*d1));
            d0 = xi0 - a0.y; d1 = xi1 - a1.y; o.y = eta * __expf(-0.5f * (d0*d0 + d1*d1));
            d0 = xi0 - a0.z; d1 = xi1 - a1.z; o.z = eta * __expf(-0.5f * (d0*d0 + d1*d1));
            d0 = xi0 - a0.w; d1 = xi1 - a1.w; o.w = eta * __expf(-0.5f * (d0*d0 + d1*d1));
            *(float4*)(row + j) = o;
        }
        for (int j = j4; j < i; ++j) {
            float d0 = xi0 - xs0[j], d1 = xi1 - xs1[j];
            row[j] = eta * __expf(-0.5f * (d0*d0 + d1*d1));
        }
        row[i] = eta + sigma2;
    }
    gbar(sense);

    // ===== phase: diag0 =====
    if (gw < MM) {
        int m = gw;
        const float* cov = g_cov + (size_t)m * NN * LDA;
        float a[32];
        #pragma unroll
        for (int j = 0; j < 32; ++j)
            a[j] = (j <= lane) ? cov[(size_t)lane * LDA + j] : 0.f;
        wfactor_inv(a, lane, g_ld + ((size_t)m * 32) * 1056, g_ldet + m * 32,
                    g_iH + ((size_t)m * 32) * 1024, g_iL + ((size_t)m * 32) * 1024);
    }
    gbar(sense);

    // ===== outer loop =====
    for (int kb = 0; kb < 16; ++kb) {
        const int k0 = kb * 64;
        const int nt1 = (NN - k0 - 32) >> 5;
        const int nt2 = (NN - k0 - 64) >> 5;

        // ---- panel1: X = A * invL1^T ----
        for (int w = gw; w < MM * nt1; w += NW) {
            const int m = w / nt1, ti = w % nt1;
            float* cov = g_cov + (size_t)m * NN * LDA;
            uint16_t* gH = g_pH + (size_t)m * NN * PP;
            uint16_t* gL = g_pL + (size_t)m * NN * PP;
            const uint16_t* iH = g_iH + ((size_t)m * 32 + 2 * kb) * 1024;
            const uint16_t* iL = g_iL + ((size_t)m * 32 + 2 * kb) * 1024;
            const int br = k0 + 32 + ti * 32;
            float c[2][4][4];
            #pragma unroll
            for (int mb = 0; mb < 2; ++mb)
                #pragma unroll
                for (int nb = 0; nb < 4; ++nb)
                    #pragma unroll
                    for (int q = 0; q < 4; ++q) c[mb][nb][q] = 0.f;
            #pragma unroll
            for (int kc = 0; kc < 32; kc += 16) {
                uint32_t aH[2][4], aL[2][4], bH[4][2], bL[4][2];
                #pragma unroll
                for (int mb = 0; mb < 2; ++mb) {
                    int r = br + mb * 16 + g;
                    float2 f;
                    f = *(const float2*)&cov[(size_t)r * LDA + k0 + kc + 2*t];
                    cvt2(f.x, f.y, aH[mb][0], aL[mb][0]);
                    f = *(const float2*)&cov[(size_t)(r + 8) * LDA + k0 + kc + 2*t];
                    cvt2(f.x, f.y, aH[mb][1], aL[mb][1]);
                    f = *(const float2*)&cov[(size_t)r * LDA + k0 + kc + 2*t + 8];
                    cvt2(f.x, f.y, aH[mb][2], aL[mb][2]);
                    f = *(const float2*)&cov[(size_t)(r + 8) * LDA + k0 + kc + 2*t + 8];
                    cvt2(f.x, f.y, aH[mb][3], aL[mb][3]);
                }
                #pragma unroll
                for (int nb = 0; nb < 4; ++nb) {
                    int n = nb * 8 + g;
                    bH[nb][0] = *(const uint32_t*)(iH + n * 32 + kc + 2*t);
                    bH[nb][1] = *(const uint32_t*)(iH + n * 32 + kc + 2*t + 8);
                    bL[nb][0] = *(const uint32_t*)(iL + n * 32 + kc + 2*t);
                    bL[nb][1] = *(const uint32_t*)(iL + n * 32 + kc + 2*t + 8);
                }
                #pragma unroll
                for (int mb = 0; mb < 2; ++mb)
                    #pragma unroll
                    for (int nb = 0; nb < 4; ++nb) {
                        hmma(c[mb][nb], aH[mb], bH[nb]);
                        hmma(c[mb][nb], aH[mb], bL[nb]);
                        hmma(c[mb][nb], aL[mb], bH[nb]);
                    }
            }
            #pragma unroll
            for (int mb = 0; mb < 2; ++mb)
                #pragma unroll
                for (int half = 0; half < 2; ++half) {
                    int r = br + mb * 16 + g + half * 8;
                    float* rowp = cov + (size_t)r * LDA + k0;
                    uint16_t* hp = gH + (size_t)r * PP;
                    uint16_t* lp = gL + (size_t)r * PP;
                    #pragma unroll
                    for (int nb = 0; nb < 4; ++nb) {
                        float2 v = make_float2(c[mb][nb][half*2], c[mb][nb][half*2+1]);
                        *(float2*)(rowp + nb*8 + 2*t) = v;
                        uint32_t h, l; cvt2(v.x, v.y, h, l);
                        *(uint32_t*)(hp + nb*8 + 2*t) = h;
                        *(uint32_t*)(lp + nb*8 + 2*t) = l;
                    }
                }
        }
        gbar(sense);

        // ---- diag2 (shuffle-based, 64 warps) ----
        if (gw < MM) {
            int m = gw;
            const float* cov = g_cov + (size_t)m * NN * LDA;
            float bb[32], dr[32];
            const float* brow = cov + (size_t)(k0 + 32 + lane) * LDA + k0;
            #pragma unroll
            for (int j = 0; j < 32; ++j) bb[j] = brow[j];
            const float* drow = brow + 32;
            #pragma unroll
            for (int j = 0; j < 32; ++j) dr[j] = drow[j];
            float a[32];
            #pragma unroll
            for (int cc = 0; cc < 32; ++cc) {
                float s = 0.f;
                #pragma unroll
                for (int p = 0; p < 32; ++p)
                    s += bb[p] * __shfl_sync(0xffffffffu, bb[p], cc);
                a[cc] = (cc <= lane) ? (dr[cc] - s) : 0.f;
            }
            wfactor_inv(a, lane,
                        g_ld + ((size_t)m * 32 + 2*kb + 1) * 1056,
                        g_ldet + m * 32 + 2*kb + 1,
                        g_iH + ((size_t)m * 32 + 2*kb + 1) * 1024,
                        g_iL + ((size_t)m * 32 + 2*kb + 1) * 1024);
        }
        gbar(sense);

        if (nt2 > 0) {
            // ---- panel2: X2 = (W - A*Bb^T) * invL2^T ----
            for (int w = gw; w < MM * nt2; w += NW) {
                const int m = w / nt2, ti = w % nt2;
                float* cov = g_cov + (size_t)m * NN * LDA;
                uint16_t* gH = g_pH + (size_t)m * NN * PP;
                uint16_t* gL = g_pL + (size_t)m * NN * PP;
                const uint16_t* iH = g_iH + ((size_t)m * 32 + 2*kb + 1) * 1024;
                const uint16_t* iL = g_iL + ((size_t)m * 32 + 2*kb + 1) * 1024;
                const int br = k0 + 64 + ti * 32;

                float c[2][4][4];
                #pragma unroll
                for (int mb = 0; mb < 2; ++mb)
                    #pragma unroll
                    for (int half = 0; half < 2; ++half) {
                        const float* rowp = cov + (size_t)(br + mb*16 + g + half*8) * LDA + k0 + 32;
                        #pragma unroll
                        for (int nb = 0; nb < 4; ++nb) {
                            float2 wv = *(const float2*)(rowp + nb*8 + 2*t);
                            c[mb][nb][half*2]     = wv.x;
                            c[mb][nb][half*2 + 1] = wv.y;
                        }
                    }
                #pragma unroll
                for (int kc = 0; kc < 32; kc += 16) {
                    uint32_t aH[2][4], aL[2][4], bH[4][2], bL[4][2];
                    #pragma unroll
                    for (int mb = 0; mb < 2; ++mb) {
                        size_t r0 = (size_t)(br + mb*16 + g) * PP + kc + 2*t;
                        size_t r8 = r0 + 8 * PP;
                        aH[mb][0] = *(const uint32_t*)(gH + r0) ^ 0x80008000u;
                        aH[mb][1] = *(const uint32_t*)(gH + r8) ^ 0x80008000u;
                        aH[mb][2] = *(const uint32_t*)(gH + r0 + 8) ^ 0x80008000u;
                        aH[mb][3] = *(const uint32_t*)(gH + r8 + 8) ^ 0x80008000u;
                        aL[mb][0] = *(const uint32_t*)(gL + r0) ^ 0x80008000u;
                        aL[mb][1] = *(const uint32_t*)(gL + r8) ^ 0x80008000u;
                        aL[mb][2] = *(const uint32_t*)(gL + r0 + 8) ^ 0x80008000u;
                        aL[mb][3] = *(const uint32_t*)(gL + r8 + 8) ^ 0x80008000u;
                    }
                    #pragma unroll
                    for (int nb = 0; nb < 4; ++nb) {
                        size_t rj = (size_t)(k0 + 32 + nb*8 + g) * PP + kc + 2*t;
                        bH[nb][0] = *(const uint32_t*)(gH + rj);
                        bH[nb][1] = *(const uint32_t*)(gH + rj + 8);
                        bL[nb][0] = *(const uint32_t*)(gL + rj);
                        bL[nb][1] = *(const uint32_t*)(gL + rj + 8);
                    }
                    #pragma unroll
                    for (int mb = 0; mb < 2; ++mb)
                        #pragma unroll
                        for (int nb = 0; nb < 4; ++nb) {
                            hmma(c[mb][nb], aH[mb], bH[nb]);
                            hmma(c[mb][nb], aH[mb], bL[nb]);
                            hmma(c[mb][nb], aL[mb], bH[nb]);
                        }
                }
                float c2[2][4][4];
                #pragma unroll
                for (int mb = 0; mb < 2; ++mb)
                    #pragma unroll
                    for (int nb = 0; nb < 4; ++nb)
                        #pragma unroll
                        for (int q = 0; q < 4; ++q) c2[mb][nb][q] = 0.f;
                #pragma unroll
                for (int kx = 0; kx < 2; ++kx) {
                    uint32_t aH[2][4], aL[2][4], bH[4][2], bL[4][2];
                    #pragma unroll
                    for (int mb = 0; mb < 2; ++mb) {
                        int n0 = 2 * kx, n1 = n0 + 1;
                        cvt2(c[mb][n0][0], c[mb][n0][1], aH[mb][0], aL[mb][0]);
                        cvt2(c[mb][n0][2], c[mb][n0][3], aH[mb][1], aL[mb][1]);
                        cvt2(c[mb][n1][0], c[mb][n1][1], aH[mb][2], aL[mb][2]);
                        cvt2(c[mb][n1][2], c[mb][n1][3], aH[mb][3], aL[mb][3]);
                    }
                    #pragma unroll
                    for (int nb = 0; nb < 4; ++nb) {
                        int n = nb * 8 + g;
                        bH[nb][0] = *(const uint32_t*)(iH + n * 32 + 16*kx + 2*t);
                        bH[nb][1] = *(const uint32_t*)(iH + n * 32 + 16*kx + 2*t + 8);
                        bL[nb][0] = *(const uint32_t*)(iL + n * 32 + 16*kx + 2*t);
                        bL[nb][1] = *(const uint32_t*)(iL + n * 32 + 16*kx + 2*t + 8);
                    }
                    #pragma unroll
                    for (int mb = 0; mb < 2; ++mb)
                        #pragma unroll
                        for (int nb = 0; nb < 4; ++nb) {
                            hmma(c2[mb][nb], aH[mb], bH[nb]);
                            hmma(c2[mb][nb], aH[mb], bL[nb]);
                            hmma(c2[mb][nb], aL[mb], bH[nb]);
                        }
                }
                #pragma unroll
                for (int mb = 0; mb < 2; ++mb)
                    #pragma unroll
                    for (int half = 0; half < 2; ++half) {
                        int r = br + mb*16 + g + half*8;
                        float* rowp = cov + (size_t)r * LDA + k0 + 32;
                        uint16_t* hp = gH + (size_t)r * PP + 32;
                        uint16_t* lp = gL + (size_t)r * PP + 32;
                        #pragma unroll
                        for (int nb = 0; nb < 4; ++nb) {
                            float2 v = make_float2(c2[mb][nb][half*2], c2[mb][nb][half*2+1]);
                            *(float2*)(rowp + nb*8 + 2*t) = v;
                            uint32_t h, l; cvt2(v.x, v.y, h, l);
                            *(uint32_t*)(hp + nb*8 + 2*t) = h;
                            *(uint32_t*)(lp + nb*8 + 2*t) = l;
                        }
                    }
            }
            gbar(sense);

            // ---- trail (K=64) + inline diag1(kb+1) on pair-0 warps ----
            const int npair = nt2 * (nt2 + 1) / 2;
            const int g0 = k0 + 64;
            for (int w = gw; w < MM * npair; w += NW) {
                const int m = w / npair, pair = w % npair;
                float* cov = g_cov + (size_t)m * NN * LDA;
                const uint16_t* gH = g_pH + (size_t)m * NN * PP;
                const uint16_t* gL = g_pL + (size_t)m * NN * PP;

                int tib = 0, rem = pair;
                while (rem >= tib + 1) { rem -= tib + 1; ++tib; }
                const int tjb = rem;
                const int i0 = tib * 32, j0 = tjb * 32;
                const bool full = (tib != tjb);

                float2 cp[2][2][4];
                if (full) {
                    #pragma unroll
                    for (int mb = 0; mb < 2; ++mb)
                        #pragma unroll
                        for (int half = 0; half < 2; ++half) {
                            const float* rowp = cov + (size_t)(g0 + i0 + mb*16 + g + half*8) * LDA + g0 + j0;
                            #pragma unroll
                            for (int nb = 0; nb < 4; ++nb)
                                cp[mb][half][nb] = *(const float2*)(rowp + nb*8 + t*2);
                        }
                }
                float c[2][4][4];
                #pragma unroll
                for (int mb = 0; mb < 2; ++mb)
                    #pragma unroll
                    for (int nb = 0; nb < 4; ++nb)
                        #pragma unroll
                        for (int q = 0; q < 4; ++q) c[mb][nb][q] = 0.f;
                #pragma unroll
                for (int kc = 0; kc < 64; kc += 16) {
                    uint32_t aH[2][4], aL[2][4], bH[4][2], bL[4][2];
                    #pragma unroll
                    for (int mb = 0; mb < 2; ++mb) {
                        size_t r0 = (size_t)(g0 + i0 + mb*16 + g) * PP + kc + 2*t;
                        size_t r8 = r0 + 8 * PP;
                        aH[mb][0] = *(const uint32_t*)(gH + r0);
                        aH[mb][1] = *(const uint32_t*)(gH + r8);
                        aH[mb][2] = *(const uint32_t*)(gH + r0 + 8);
                        aH[mb][3] = *(const uint32_t*)(gH + r8 + 8);
                        aL[mb][0] = *(const uint32_t*)(gL + r0);
                        aL[mb][1] = *(const uint32_t*)(gL + r8);
                        aL[mb][2] = *(const uint32_t*)(gL + r0 + 8);
                        aL[mb][3] = *(const uint32_t*)(gL + r8 + 8);
                    }
                    #pragma unroll
                    for (int nb = 0; nb < 4; ++nb) {
                        size_t rj = (size_t)(g0 + j0 + nb*8 + g) * PP + kc + 2*t;
                        bH[nb][0] = *(const uint32_t*)(gH + rj);
                        bH[nb][1] = *(const uint32_t*)(gH + rj + 8);
                        bL[nb][0] = *(const uint32_t*)(gL + rj);
                        bL[nb][1] = *(const uint32_t*)(gL + rj + 8);
                    }
                    #pragma unroll
                    for (int mb = 0; mb < 2; ++mb)
                        #pragma unroll
                        for (int nb = 0; nb < 4; ++nb) {
                            hmma(c[mb][nb], aH[mb], bH[nb]);
                            hmma(c[mb][nb], aH[mb], bL[nb]);
                            hmma(c[mb][nb], aL[mb], bH[nb]);
                        }
                }
                if (full) {
                    #pragma unroll
                    for (int mb = 0; mb < 2; ++mb)
                        #pragma unroll
                        for (int half = 0; half < 2; ++half) {
                            float* rowp = cov + (size_t)(g0 + i0 + mb*16 + g + half*8) * LDA + g0 + j0;
                            #pragma unroll
                            for (int nb = 0; nb < 4; ++nb) {
                                float2 v = cp[mb][half][nb];
                                v.x -= c[mb][nb][half*2];
                                v.y -= c[mb][nb][half*2 + 1];
                                *(float2*)(rowp + nb*8 + t*2) = v;
                            }
                        }
                } else {
                    #pragma unroll
                    for (int mb = 0; mb < 2; ++mb)
                        #pragma unroll
                        for (int half = 0; half < 2; ++half) {
                            int i_loc = i0 + mb*16 + g + half*8;
                            float* row = cov + (size_t)(g0 + i_loc) * LDA + g0;
                            #pragma unroll
                            for (int nb = 0; nb < 4; ++nb) {
                                int j = j0 + nb*8 + t*2;
                                float cx = c[mb][nb][half*2];
                                float cy = c[mb][nb][half*2 + 1];
                                if (j + 1 <= i_loc) {
                                    float2 v = *(float2*)(row + j);
                                    v.x -= cx; v.y -= cy;
                                    *(float2*)(row + j) = v;
                                } else if (j <= i_loc) {
                                    row[j] -= cx;
                                }
                            }
                        }
                }
                if (pair == 0) {
                    __threadfence_block();
                    __syncwarp();
                    float a[32];
                    const float* rr = cov + (size_t)(g0 + lane) * LDA + g0;
                    #pragma unroll
                    for (int j = 0; j < 32; ++j)
                        a[j] = (j <= lane) ? rr[j] : 0.f;
                    wfactor_inv(a, lane,
                                g_ld + ((size_t)m * 32 + 2*(kb+1)) * 1056,
                                g_ldet + m * 32 + 2*(kb+1),
                                g_iH + ((size_t)m * 32 + 2*(kb+1)) * 1024,
                                g_iL + ((size_t)m * 32 + 2*(kb+1)) * 1024);
                }
            }
            gbar(sense);
        }
    }

    // ===== phase: forward substitution + output (one block per matrix) =====
    if (blockIdx.x < MM) {
        const int m = blockIdx.x;
        float* cov = g_cov + (size_t)m * NN * LDA;
        const float beta = g_scal[m*8+0];

        for (int i = tid; i < NN; i += 256) s_rhs[i] = y[i] - beta;
        __syncthreads();

        for (int kb2 = 0; kb2 < 32; ++kb2) {
            const int k0 = kb2 * 32;
            if (tid < 32) {
                const float* lrow = g_ld + ((size_t)m * 32 + kb2) * 1056 + lane * 33;
                float lr[32];
                #pragma unroll
                for (int j = 0; j < 32; ++j) lr[j] = (j <= lane) ? lrow[j] : 0.f;
                float tt = s_rhs[k0 + lane];
                #pragma unroll
                for (int j = 0; j < 32; ++j) {
                    if (lane == j) tt /= lr[j];
                    float sj = __shfl_sync(0xffffffffu, tt, j);
                    if (lane > j) tt -= sj * lr[j];
                }
                s_rhs[k0 + lane] = tt;
            }
            __syncthreads();
            for (int i = k0 + 32 + tid; i < NN; i += 256) {
                const float* row = cov + (size_t)i * LDA + k0;
                float acc = 0.f;
                #pragma unroll
                for (int w8 = 0; w8 < 8; ++w8) {
                    float4 c4 = ((const float4*)row)[w8];
                    acc += c4.x * s_rhs[k0 + 4*w8]     + c4.y * s_rhs[k0 + 4*w8 + 1]
                         + c4.z * s_rhs[k0 + 4*w8 + 2] + c4.w * s_rhs[k0 + 4*w8 + 3];
                }
                s_rhs[i] -= acc;
            }
            __syncthreads();
        }

        float q = 0.f;
        for (int i = tid; i < NN; i += 256) { float v = s_rhs[i]; q += v * v; }
        s_red[tid] = q;
        __syncthreads();
        for (int s = 128; s; s >>= 1) {
            if (tid < s) s_red[tid] += s_red[tid + s];
            __syncthreads();
        }
        if (tid == 0) {
            float ldsum = 0.f;
            for (int d = 0; d < 32; ++d) ldsum += g_ldet[m * 32 + d];
            const float LN2PI = 1.8378770664093453f;
            out[m] = -0.5f * (s_red[0] + 2.f * ldsum + 1024.f * LN2PI) + g_scal[m*8+5];
        }
    }
}

extern "C" void kernel_launch(void* const* d_in, const int* in_sizes, int n_in,
                              void* d_out, int out_size)
{
    (void)in_sizes; (void)n_in; (void)out_size;
    static int grid = 0;
    if (grid == 0) {
        int dev = 0, smc = 0, mb = 0;
        cudaGetDevice(&dev);
        cudaDeviceGetAttribute(&smc, cudaDevAttrMultiProcessorCount, dev);
        cudaOccupancyMaxActiveBlocksPerMultiprocessor(&mb, k_persist, 256, 0);
        if (mb < 1) mb = 1;
        if (mb > 2) mb = 2;
        grid = smc * mb;
        if (grid < MM) grid = MM;   // need >= 64 blocks for finish phase
    }
    k_persist<<<grid, 256>>>(
        (const float*)d_in[0], (const float*)d_in[1], (const float*)d_in[2],
        (const float*)d_in[3], (const float*)d_in[4],
        (const float*)d_in[5], (const float*)d_in[6],
        (const float*)d_in[7], (const float*)d_in[8],
        (const float*)d_in[9], (const float*)d_in[10],
        (const float*)d_in[11], (const float*)d_in[12],
        (float*)d_out);
}

// round 17
// speedup vs baseline: 1.2276x; 1.2276x over previous
#include <cuda_runtime.h>
#include <cuda_bf16.h>
#include <math.h>
#include <stdint.h>

#define NN 1024
#define MM 64
#define LDA 1040
#define PP 64

__device__ float    g_cov[(size_t)MM * NN * LDA];
__device__ uint16_t g_pH[(size_t)MM * NN * PP];
__device__ uint16_t g_pL[(size_t)MM * NN * PP];
__device__ float    g_ld[(size_t)MM * 32 * 1056];
__device__ uint16_t g_iH[(size_t)MM * 32 * 1024];
__device__ uint16_t g_iL[(size_t)MM * 32 * 1024];
__device__ float    g_scal[MM * 8];
__device__ float    g_ldet[MM * 32];

__device__ __forceinline__ void hmma(float* c, const uint32_t* a, const uint32_t* b) {
    asm volatile("mma.sync.aligned.m16n8k16.row.col.f32.bf16.bf16.f32 "
        "{%0,%1,%2,%3},{%4,%5,%6,%7},{%8,%9},{%0,%1,%2,%3};"
        : "+f"(c[0]), "+f"(c[1]), "+f"(c[2]), "+f"(c[3])
        : "r"(a[0]), "r"(a[1]), "r"(a[2]), "r"(a[3]), "r"(b[0]), "r"(b[1]));
}
__device__ __forceinline__ void cvt2(float xx, float yy, uint32_t& h, uint32_t& l) {
    __nv_bfloat16 h0 = __float2bfloat16(xx), h1 = __float2bfloat16(yy);
    __nv_bfloat16 l0 = __float2bfloat16(xx - __bfloat162float(h0));
    __nv_bfloat16 l1 = __float2bfloat16(yy - __bfloat162float(h1));
    h = (uint32_t)__bfloat16_as_ushort(h0) | ((uint32_t)__bfloat16_as_ushort(h1) << 16);
    l = (uint32_t)__bfloat16_as_ushort(l0) | ((uint32_t)__bfloat16_as_ushort(l1) << 16);
}
__device__ __forceinline__ float sp_(float x) {
    return fmaxf(x, 0.f) + log1pf(expf(-fabsf(x))) + 1e-7f;
}
__device__ __forceinline__ float log_normal_(float v, float mean, float s, float eps) {
    const float C = -0.91893853320467274178f;
    float d = v - mean;
    return -d * d / (2.f * s * s + eps) - logf(s) + C;
}
__device__ __forceinline__ float log_lognormal_(float v, float mean, float s, float eps) {
    const float C = -0.91893853320467274178f;
    float lv = logf(v);
    float d = lv - mean;
    return -d * d / (2.f * s * s + eps) - lv - logf(s) + C;
}

// register/shuffle-only: factor 32x32 (a[j]=row 'lane', zeros above diag) + invert (validated R16)
__device__ __forceinline__ void wfactor_inv(float* a, int lane, float* gld, float* ldet,
                                            uint16_t* oH, uint16_t* oL)
{
    #pragma unroll
    for (int j = 0; j < 32; ++j) {
        float dj = __shfl_sync(0xffffffffu, a[j], j);
        float sj = sqrtf(dj);
        float lrj = (lane == j) ? sj : a[j] / sj;
        a[j] = lrj;
        #pragma unroll
        for (int cc = j + 1; cc < 32; ++cc)
            a[cc] -= lrj * __shfl_sync(0xffffffffu, lrj, cc);
    }
    #pragma unroll
    for (int j = 0; j < 32; ++j)
        if (j <= lane) gld[lane * 33 + j] = a[j];
    float ld = logf(a[lane]);
    #pragma unroll
    for (int o = 16; o; o >>= 1) ld += __shfl_xor_sync(0xffffffffu, ld, o);
    if (lane == 0) *ldet = ld;
    float xv[32];
    #pragma unroll
    for (int i = 0; i < 32; ++i) {
        float s = (i == lane) ? 1.f : 0.f;
        #pragma unroll
        for (int p = 0; p < 32; ++p)
            if (p < i)
                s -= __shfl_sync(0xffffffffu, a[p], i) * xv[p];
        float dii = __shfl_sync(0xffffffffu, a[i], i);
        xv[i] = s / dii;
    }
    #pragma unroll
    for (int i = 0; i < 32; ++i) {
        __nv_bfloat16 h = __float2bfloat16(xv[i]);
        __nv_bfloat16 l = __float2bfloat16(xv[i] - __bfloat162float(h));
        oH[i * 32 + lane] = __bfloat16_as_ushort(h);
        oL[i * 32 + lane] = __bfloat16_as_ushort(l);
    }
}

// ---------------- cov build + scalars (grid: (2, MM)) ----------------
extern "C" __global__ void __launch_bounds__(512, 1)
k_build(const float* __restrict__ x, const float* __restrict__ z,
    const float* qbm, const float* qbs, const float* qsm, const float* qss,
    const float* qem, const float* qes, const float* qzm, const float* qzs,
    const float* qnm, const float* qns)
{
    __shared__ float xs[2048];
    __shared__ float sc[8];
    const int m = blockIdx.y, par = blockIdx.x, tid = threadIdx.x;
    float* cov = g_cov + (size_t)m * NN * LDA;
    if (tid == 0) {
        float s0 = sp_(sqrtf(logf(2.f)));
        float z0 = z[m*5+0], z1 = z[m*5+1], z2 = z[m*5+2], z3 = z[m*5+3], z4 = z[m*5+4];
        float sps = sp_(*qss), spb = sp_(*qbs), spe = sp_(*qes), spz = sp_(*qzs), spn = sp_(*qns);
        float sigma2 = expf(z0 * sps + *qsm);
        float beta   = z1 * spb + *qbm;
        float eta    = expf(z2 * spe + *qem);
        float lsZ    = expf(z3 * spz + *qzm);
        float lsN    = expf(z4 * spn + *qnm);
        float lp = log_normal_(beta, 0.f, 1.f, 1e-5f)
                 + log_lognormal_(sigma2, 1.f, s0, 1e-6f)
                 + log_lognormal_(eta,    1.f, s0, 1e-6f)
                 + log_lognormal_(lsZ,    1.f, s0, 1e-6f)
                 + log_lognormal_(lsN,    1.f, s0, 1e-6f);
        float lq = log_normal_(beta, *qbm, spb, 1e-5f)
                 + log_lognormal_(sigma2, *qsm, sps, 1e-6f)
                 + log_lognormal_(eta,    *qem, spe, 1e-6f)
                 + log_lognormal_(lsZ,    *qzm, spz, 1e-6f)
                 + log_lognormal_(lsN,    *qnm, spn, 1e-6f);
        sc[0] = beta; sc[1] = sigma2; sc[2] = eta;
        sc[3] = lsZ;  sc[4] = lsN;    sc[5] = lp - lq;
        if (par == 0) {
            #pragma unroll
            for (int q = 0; q < 6; ++q) g_scal[m*8+q] = sc[q];
        }
    }
    __syncthreads();
    const float eta = sc[2], sigma2 = sc[1], lsZ = sc[3], lsN = sc[4];
    for (int i = tid; i < NN; i += 512) {
        xs[i]      = x[2*i]   / lsZ;
        xs[NN + i] = x[2*i+1] / lsN;
    }
    __syncthreads();
    const float* xs0 = xs;
    const float* xs1 = xs + NN;
    int i = par + 2 * tid;
    float xi0 = xs0[i], xi1 = xs1[i];
    float* row = cov + (size_t)i * LDA;
    int j4 = i & ~3;
    for (int j = 0; j < j4; j += 4) {
        float4 a0 = *(const float4*)(xs0 + j);
        float4 a1 = *(const float4*)(xs1 + j);
        float4 o; float d0, d1;
        d0 = xi0 - a0.x; d1 = xi1 - a1.x; o.x = eta * __expf(-0.5f * (d0*d0 + d1*d1));
        d0 = xi0 - a0.y; d1 = xi1 - a1.y; o.y = eta * __expf(-0.5f * (d0*d0 + d1*d1));
        d0 = xi0 - a0.z; d1 = xi1 - a1.z; o.z = eta * __expf(-0.5f * (d0*d0 + d1*d1));
        d0 = xi0 - a0.w; d1 = xi1 - a1.w; o.w = eta * __expf(-0.5f * (d0*d0 + d1*d1));
        *(float4*)(row + j) = o;
    }
    for (int j = j4; j < i; ++j) {
        float d0 = xi0 - xs0[j], d1 = xi1 - xs1[j];
        row[j] = eta * __expf(-0.5f * (d0*d0 + d1*d1));
    }
    row[i] = eta + sigma2;
}

// ---------------- initial diag (grid: 8 blocks x 256) ----------------
extern "C" __global__ void __launch_bounds__(256, 2)
k_diag0()
{
    const int gw = blockIdx.x * 8 + (threadIdx.x >> 5);
    const int lane = threadIdx.x & 31;
    if (gw >= MM) return;
    const int m = gw;
    const float* cov = g_cov + (size_t)m * NN * LDA;
    float a[32];
    #pragma unroll
    for (int j = 0; j < 32; ++j)
        a[j] = (j <= lane) ? cov[(size_t)lane * LDA + j] : 0.f;
    wfactor_inv(a, lane, g_ld + ((size_t)m * 32) * 1056, g_ldet + m * 32,
                g_iH + ((size_t)m * 32) * 1024, g_iL + ((size_t)m * 32) * 1024);
}

// ---------------- panel1 (flattened): X = A*invL1^T ; ti==0 warp does diag2 ----------------
extern "C" __global__ void __launch_bounds__(256, 2)
k_panel1(int kb, int nt1)
{
    const int tid = threadIdx.x;
    const int wid = tid >> 5, lane = tid & 31;
    const int g = lane >> 2, t = lane & 3;
    const int w = blockIdx.x * 8 + wid;
    if (w >= MM * nt1) return;
    const int m = w / nt1, ti = w % nt1;
    const int k0 = kb * 64;
    float* cov = g_cov + (size_t)m * NN * LDA;
    uint16_t* gH = g_pH + (size_t)m * NN * PP;
    uint16_t* gL = g_pL + (size_t)m * NN * PP;
    const uint16_t* iH = g_iH + ((size_t)m * 32 + 2 * kb) * 1024;
    const uint16_t* iL = g_iL + ((size_t)m * 32 + 2 * kb) * 1024;

    const int br = k0 + 32 + ti * 32;
    float c[2][4][4];
    #pragma unroll
    for (int mb = 0; mb < 2; ++mb)
        #pragma unroll
        for (int nb = 0; nb < 4; ++nb)
            #pragma unroll
            for (int q = 0; q < 4; ++q) c[mb][nb][q] = 0.f;

    #pragma unroll
    for (int kc = 0; kc < 32; kc += 16) {
        uint32_t aH[2][4], aL[2][4], bH[4][2], bL[4][2];
        #pragma unroll
        for (int mb = 0; mb < 2; ++mb) {
            int r = br + mb * 16 + g;
            float2 f;
            f = *(const float2*)&cov[(size_t)r * LDA + k0 + kc + 2*t];
            cvt2(f.x, f.y, aH[mb][0], aL[mb][0]);
            f = *(const float2*)&cov[(size_t)(r + 8) * LDA + k0 + kc + 2*t];
            cvt2(f.x, f.y, aH[mb][1], aL[mb][1]);
            f = *(const float2*)&cov[(size_t)r * LDA + k0 + kc + 2*t + 8];
            cvt2(f.x, f.y, aH[mb][2], aL[mb][2]);
            f = *(const float2*)&cov[(size_t)(r + 8) * LDA + k0 + kc + 2*t + 8];
            cvt2(f.x, f.y, aH[mb][3], aL[mb][3]);
        }
        #pragma unroll
        for (int nb = 0; nb < 4; ++nb) {
            int n = nb * 8 + g;
            bH[nb][0] = *(const uint32_t*)(iH + n * 32 + kc + 2*t);
            bH[nb][1] = *(const uint32_t*)(iH + n * 32 + kc + 2*t + 8);
            bL[nb][0] = *(const uint32_t*)(iL + n * 32 + kc + 2*t);
            bL[nb][1] = *(const uint32_t*)(iL + n * 32 + kc + 2*t + 8);
        }
        #pragma unroll
        for (int mb = 0; mb < 2; ++mb)
            #pragma unroll
            for (int nb = 0; nb < 4; ++nb) {
                hmma(c[mb][nb], aH[mb], bH[nb]);
                hmma(c[mb][nb], aH[mb], bL[nb]);
                hmma(c[mb][nb], aL[mb], bH[nb]);
            }
    }
    #pragma unroll
    for (int mb = 0; mb < 2; ++mb)
        #pragma unroll
        for (int half = 0; half < 2; ++half) {
            int r = br + mb * 16 + g + half * 8;
            float* rowp = cov + (size_t)r * LDA + k0;
            uint16_t* hp = gH + (size_t)r * PP;
            uint16_t* lp = gL + (size_t)r * PP;
            #pragma unroll
            for (int nb = 0; nb < 4; ++nb) {
                float2 v = make_float2(c[mb][nb][half*2], c[mb][nb][half*2+1]);
                *(float2*)(rowp + nb*8 + 2*t) = v;
                uint32_t h, l; cvt2(v.x, v.y, h, l);
                *(uint32_t*)(hp + nb*8 + 2*t) = h;
                *(uint32_t*)(lp + nb*8 + 2*t) = l;
            }
        }

    if (ti == 0) {
        __threadfence_block();
        __syncwarp();
        float bb[32], dr[32];
        const float* brow = cov + (size_t)(k0 + 32 + lane) * LDA + k0;
        #pragma unroll
        for (int j = 0; j < 32; ++j) bb[j] = brow[j];
        #pragma unroll
        for (int j = 0; j < 32; ++j) dr[j] = brow[32 + j];
        float a[32];
        #pragma unroll
        for (int cc = 0; cc < 32; ++cc) {
            float s = 0.f;
            #pragma unroll
            for (int p = 0; p < 32; ++p)
                s += bb[p] * __shfl_sync(0xffffffffu, bb[p], cc);
            a[cc] = (cc <= lane) ? (dr[cc] - s) : 0.f;
        }
        wfactor_inv(a, lane,
                    g_ld + ((size_t)m * 32 + 2*kb + 1) * 1056,
                    g_ldet + m * 32 + 2*kb + 1,
                    g_iH + ((size_t)m * 32 + 2*kb + 1) * 1024,
                    g_iL + ((size_t)m * 32 + 2*kb + 1) * 1024);
    }
}

// ---------------- panel2 (flattened): X2 = (W - A*Bb^T) * invL2^T ----------------
extern "C" __global__ void __launch_bounds__(256, 2)
k_panel2(int kb, int nt2)
{
    const int tid = threadIdx.x;
    const int wid = tid >> 5, lane = tid & 31;
    const int g = lane >> 2, t = lane & 3;
    const int w = blockIdx.x * 8 + wid;
    if (w >= MM * nt2) return;
    const int m = w / nt2, ti = w % nt2;
    const int k0 = kb * 64;
    const int br = k0 + 64 + ti * 32;
    float* cov = g_cov + (size_t)m * NN * LDA;
    uint16_t* gH = g_pH + (size_t)m * NN * PP;
    uint16_t* gL = g_pL + (size_t)m * NN * PP;
    const uint16_t* iH = g_iH + ((size_t)m * 32 + 2*kb + 1) * 1024;
    const uint16_t* iL = g_iL + ((size_t)m * 32 + 2*kb + 1) * 1024;

    float c[2][4][4];
    #pragma unroll
    for (int mb = 0; mb < 2; ++mb)
        #pragma unroll
        for (int half = 0; half < 2; ++half) {
            const float* rowp = cov + (size_t)(br + mb*16 + g + half*8) * LDA + k0 + 32;
            #pragma unroll
            for (int nb = 0; nb < 4; ++nb) {
                float2 wv = *(const float2*)(rowp + nb*8 + 2*t);
                c[mb][nb][half*2]     = wv.x;
                c[mb][nb][half*2 + 1] = wv.y;
            }
        }

    #pragma unroll
    for (int kc = 0; kc < 32; kc += 16) {
        uint32_t aH[2][4], aL[2][4], bH[4][2], bL[4][2];
        #pragma unroll
        for (int mb = 0; mb < 2; ++mb) {
            size_t r0 = (size_t)(br + mb*16 + g) * PP + kc + 2*t;
            size_t r8 = r0 + 8 * PP;
            aH[mb][0] = *(const uint32_t*)(gH + r0) ^ 0x80008000u;
            aH[mb][1] = *(const uint32_t*)(gH + r8) ^ 0x80008000u;
            aH[mb][2] = *(const uint32_t*)(gH + r0 + 8) ^ 0x80008000u;
            aH[mb][3] = *(const uint32_t*)(gH + r8 + 8) ^ 0x80008000u;
            aL[mb][0] = *(const uint32_t*)(gL + r0) ^ 0x80008000u;
            aL[mb][1] = *(const uint32_t*)(gL + r8) ^ 0x80008000u;
            aL[mb][2] = *(const uint32_t*)(gL + r0 + 8) ^ 0x80008000u;
            aL[mb][3] = *(const uint32_t*)(gL + r8 + 8) ^ 0x80008000u;
        }
        #pragma unroll
        for (int nb = 0; nb < 4; ++nb) {
            size_t rj = (size_t)(k0 + 32 + nb*8 + g) * PP + kc + 2*t;
            bH[nb][0] = *(const uint32_t*)(gH + rj);
            bH[nb][1] = *(const uint32_t*)(gH + rj + 8);
            bL[nb][0] = *(const uint32_t*)(gL + rj);
            bL[nb][1] = *(const uint32_t*)(gL + rj + 8);
        }
        #pragma unroll
        for (int mb = 0; mb < 2; ++mb)
            #pragma unroll
            for (int nb = 0; nb < 4; ++nb) {
                hmma(c[mb][nb], aH[mb], bH[nb]);
                hmma(c[mb][nb], aH[mb], bL[nb]);
                hmma(c[mb][nb], aL[mb], bH[nb]);
            }
    }

    float c2[2][4][4];
    #pragma unroll
    for (int mb = 0; mb < 2; ++mb)
        #pragma unroll
        for (int nb = 0; nb < 4; ++nb)
            #pragma unroll
            for (int q = 0; q < 4; ++q) c2[mb][nb][q] = 0.f;

    #pragma unroll
    for (int kx = 0; kx < 2; ++kx) {
        uint32_t aH[2][4], aL[2][4], bH[4][2], bL[4][2];
        #pragma unroll
        for (int mb = 0; mb < 2; ++mb) {
            int n0 = 2 * kx, n1 = n0 + 1;
            cvt2(c[mb][n0][0], c[mb][n0][1], aH[mb][0], aL[mb][0]);
            cvt2(c[mb][n0][2], c[mb][n0][3], aH[mb][1], aL[mb][1]);
            cvt2(c[mb][n1][0], c[mb][n1][1], aH[mb][2], aL[mb][2]);
            cvt2(c[mb][n1][2], c[mb][n1][3], aH[mb][3], aL[mb][3]);
        }
        #pragma unroll
        for (int nb = 0; nb < 4; ++nb) {
            int n = nb * 8 + g;
            bH[nb][0] = *(const uint32_t*)(iH + n * 32 + 16*kx + 2*t);
            bH[nb][1] = *(const uint32_t*)(iH + n * 32 + 16*kx + 2*t + 8);
            bL[nb][0] = *(const uint32_t*)(iL + n * 32 + 16*kx + 2*t);
            bL[nb][1] = *(const uint32_t*)(iL + n * 32 + 16*kx + 2*t + 8);
        }
        #pragma unroll
        for (int mb = 0; mb < 2; ++mb)
            #pragma unroll
            for (int nb = 0; nb < 4; ++nb) {
                hmma(c2[mb][nb], aH[mb], bH[nb]);
                hmma(c2[mb][nb], aH[mb], bL[nb]);
                hmma(c2[mb][nb], aL[mb], bH[nb]);
            }
    }

    #pragma unroll
    for (int mb = 0; mb < 2; ++mb)
        #pragma unroll
        for (int half = 0; half < 2; ++half) {
            int r = br + mb*16 + g + half*8;
            float* rowp = cov + (size_t)r * LDA + k0 + 32;
            uint16_t* hp = gH + (size_t)r * PP + 32;
            uint16_t* lp = gL + (size_t)r * PP + 32;
            #pragma unroll
            for (int nb = 0; nb < 4; ++nb) {
                float2 v = make_float2(c2[mb][nb][half*2], c2[mb][nb][half*2+1]);
                *(float2*)(rowp + nb*8 + 2*t) = v;
                uint32_t h, l; cvt2(v.x, v.y, h, l);
                *(uint32_t*)(hp + nb*8 + 2*t) = h;
                *(uint32_t*)(lp + nb*8 + 2*t) = l;
            }
        }
}

// ---------------- trail (flattened, K=64) + diag1(kb+1) on pair==0 warps ----------------
extern "C" __global__ void __launch_bounds__(256, 2)
k_trail(int kb, int npair)
{
    const int tid = threadIdx.x;
    const int wid = tid >> 5, lane = tid & 31;
    const int w = blockIdx.x * 8 + wid;
    if (w >= MM * npair) return;
    const int m = w / npair, pair = w % npair;
    const int k0 = kb * 64;
    const int g0 = k0 + 64;
    const int nt = NN - g0;

    float* cov = g_cov + (size_t)m * NN * LDA;
    const uint16_t* gH = g_pH + (size_t)m * NN * PP;
    const uint16_t* gL = g_pL + (size_t)m * NN * PP;
    const int g = lane >> 2, t = lane & 3;

    int tib = 0, rem = pair;
    while (rem >= tib + 1) { rem -= tib + 1; ++tib; }
    const int tjb = rem;
    const int i0 = tib * 32, j0 = tjb * 32;
    const bool full = (tib != tjb);

    float2 cp[2][2][4];
    if (full) {
        #pragma unroll
        for (int mb = 0; mb < 2; ++mb)
            #pragma unroll
            for (int half = 0; half < 2; ++half) {
                const float* rowp = cov + (size_t)(g0 + i0 + mb*16 + g + half*8) * LDA + g0 + j0;
                #pragma unroll
                for (int nb = 0; nb < 4; ++nb)
                    cp[mb][half][nb] = *(const float2*)(rowp + nb*8 + t*2);
            }
    }

    float c[2][4][4];
    #pragma unroll
    for (int mb = 0; mb < 2; ++mb)
        #pragma unroll
        for (int nb = 0; nb < 4; ++nb)
            #pragma unroll
            for (int q = 0; q < 4; ++q) c[mb][nb][q] = 0.f;

    #pragma unroll
    for (int kc = 0; kc < 64; kc += 16) {
        uint32_t aH[2][4], aL[2][4], bH[4][2], bL[4][2];
        #pragma unroll
        for (int mb = 0; mb < 2; ++mb) {
            size_t r0 = (size_t)(g0 + i0 + mb*16 + g) * PP + kc + 2*t;
            size_t r8 = r0 + 8 * PP;
            aH[mb][0] = *(const uint32_t*)(gH + r0);
            aH[mb][1] = *(const uint32_t*)(gH + r8);
            aH[mb][2] = *(const uint32_t*)(gH + r0 + 8);
            aH[mb][3] = *(const uint32_t*)(gH + r8 + 8);
            aL[mb][0] = *(const uint32_t*)(gL + r0);
            aL[mb][1] = *(const uint32_t*)(gL + r8);
            aL[mb][2] = *(const uint32_t*)(gL + r0 + 8);
            aL[mb][3] = *(const uint32_t*)(gL + r8 + 8);
        }
        #pragma unroll
        for (int nb = 0; nb < 4; ++nb) {
            size_t rj = (size_t)(g0 + j0 + nb*8 + g) * PP + kc + 2*t;
            bH[nb][0] = *(const uint32_t*)(gH + rj);
            bH[nb][1] = *(const uint32_t*)(gH + rj + 8);
            bL[nb][0] = *(const uint32_t*)(gL + rj);
            bL[nb][1] = *(const uint32_t*)(gL + rj + 8);
        }
        #pragma unroll
        for (int mb = 0; mb < 2; ++mb)
            #pragma unroll
            for (int nb = 0; nb < 4; ++nb) {
                hmma(c[mb][nb], aH[mb], bH[nb]);
                hmma(c[mb][nb], aH[mb], bL[nb]);
                hmma(c[mb][nb], aL[mb], bH[nb]);
            }
    }

    if (full) {
        #pragma unroll
        for (int mb = 0; mb < 2; ++mb)
            #pragma unroll
            for (int half = 0; half < 2; ++half) {
                float* rowp = cov + (size_t)(g0 + i0 + mb*16 + g + half*8) * LDA + g0 + j0;
                #pragma unroll
                for (int nb = 0; nb < 4; ++nb) {
                    float2 v = cp[mb][half][nb];
                    v.x -= c[mb][nb][half*2];
                    v.y -= c[mb][nb][half*2 + 1];
                    *(float2*)(rowp + nb*8 + t*2) = v;
                }
            }
    } else {
        #pragma unroll
        for (int mb = 0; mb < 2; ++mb)
            #pragma unroll
            for (int half = 0; half < 2; ++half) {
                int i_loc = i0 + mb*16 + g + half*8;
                float* row = cov + (size_t)(g0 + i_loc) * LDA + g0;
                #pragma unroll
                for (int nb = 0; nb < 4; ++nb) {
                    int j = j0 + nb*8 + t*2;
                    float cx = c[mb][nb][half*2];
                    float cy = c[mb][nb][half*2 + 1];
                    if (j + 1 <= i_loc) {
                        float2 v = *(float2*)(row + j);
                        v.x -= cx; v.y -= cy;
                        *(float2*)(row + j) = v;
                    } else if (j <= i_loc) {
                        row[j] -= cx;
                    }
                }
            }
    }
    (void)nt;

    if (pair == 0) {
        __threadfence_block();
        __syncwarp();
        float a[32];
        const float* rr = cov + (size_t)(g0 + lane) * LDA + g0;
        #pragma unroll
        for (int j = 0; j < 32; ++j)
            a[j] = (j <= lane) ? rr[j] : 0.f;
        wfactor_inv(a, lane,
                    g_ld + ((size_t)m * 32 + 2*(kb+1)) * 1056,
                    g_ldet + m * 32 + 2*(kb+1),
                    g_iH + ((size_t)m * 32 + 2*(kb+1)) * 1024,
                    g_iL + ((size_t)m * 32 + 2*(kb+1)) * 1024);
    }
}

// ---------------- forward substitution + output (grid: MM) ----------------
extern "C" __global__ void __launch_bounds__(512, 1)
k_finish(const float* __restrict__ y, float* __restrict__ out)
{
    __shared__ float rhs[NN];
    __shared__ float red[512];
    const int m = blockIdx.x, tid = threadIdx.x, lane = tid & 31;
    float* cov = g_cov + (size_t)m * NN * LDA;
    const float beta = g_scal[m*8+0];

    for (int i = tid; i < NN; i += 512) rhs[i] = y[i] - beta;
    __syncthreads();

    for (int kb2 = 0; kb2 < 32; ++kb2) {
        const int k0 = kb2 * 32;
        if (tid < 32) {
            const float* lrow = g_ld + ((size_t)m * 32 + kb2) * 1056 + lane * 33;
            float lr[32];
            #pragma unroll
            for (int j = 0; j < 32; ++j) lr[j] = (j <= lane) ? lrow[j] : 0.f;
            float t = rhs[k0 + lane];
            #pragma unroll
            for (int j = 0; j < 32; ++j) {
                if (lane == j) t /= lr[j];
                float sj = __shfl_sync(0xffffffffu, t, j);
                if (lane > j) t -= sj * lr[j];
            }
            rhs[k0 + lane] = t;
        }
        __syncthreads();
        for (int i = k0 + 32 + tid; i < NN; i += 512) {
            const float* row = cov + (size_t)i * LDA + k0;
            float acc = 0.f;
            #pragma unroll
            for (int w = 0; w < 8; ++w) {
                float4 c4 = ((const float4*)row)[w];
                acc += c4.x * rhs[k0 + 4*w]     + c4.y * rhs[k0 + 4*w + 1]
                     + c4.z * rhs[k0 + 4*w + 2] + c4.w * rhs[k0 + 4*w + 3];
            }
            rhs[i] -= acc;
        }
        __syncthreads();
    }

    float q = 0.f;
    for (int i = tid; i < NN; i += 512) { float v = rhs[i]; q += v * v; }
    red[tid] = q;
    __syncthreads();
    for (int s = 256; s; s >>= 1) {
        if (tid < s) red[tid] += red[tid + s];
        __syncthreads();
    }
    if (tid == 0) {
        float ldsum = 0.f;
        for (int d = 0; d < 32; ++d) ldsum += g_ldet[m * 32 + d];
        const float LN2PI = 1.8378770664093453f;
        out[m] = -0.5f * (red[0] + 2.f * ldsum + 1024.f * LN2PI) + g_scal[m*8+5];
    }
}

extern "C" void kernel_launch(void* const* d_in, const int* in_sizes, int n_in,
                              void* d_out, int out_size)
{
    (void)in_sizes; (void)n_in; (void)out_size;
    const float* x = (const float*)d_in[0];
    const float* y = (const float*)d_in[1];
    const float* z = (const float*)d_in[2];

    k_build<<<dim3(2, MM), 512>>>(x, z,
        (const float*)d_in[3], (const float*)d_in[4],
        (const float*)d_in[5], (const float*)d_in[6],
        (const float*)d_in[7], (const float*)d_in[8],
        (const float*)d_in[9], (const float*)d_in[10],
        (const float*)d_in[11], (const float*)d_in[12]);
    k_diag0<<<8, 256>>>();

    for (int kb = 0; kb < 16; ++kb) {
        int nt1 = 31 - 2 * kb;
        k_panel1<<<(MM * nt1 + 7) / 8, 256>>>(kb, nt1);
        int nt2 = 30 - 2 * kb;
        if (nt2 > 0) {
            k_panel2<<<(MM * nt2 + 7) / 8, 256>>>(kb, nt2);
            int npair = nt2 * (nt2 + 1) / 2;
            k_trail<<<(MM * npair + 7) / 8, 256>>>(kb, npair);
        }
    }
    k_finish<<<MM, 512>>>(y, (float*)d_out);
}